// round 3
// baseline (speedup 1.0000x reference)
#include <cuda_runtime.h>
#include <cuda_fp16.h>
#include <mma.h>

// Problem constants (fixed by the dataset)
#define T_STEPS 8
#define N_NODES 50000
#define E_EDGES 800000
#define DD 64
#define NPART ((N_NODES + 255) / 256)   // 196 scan blocks

// -------- scratch (static __device__ arrays; no allocation allowed) --------
__device__ __half g_y[(size_t)T_STEPS * N_NODES * DD];   // 51.2 MB, fp16 y = x@W
__device__ int    g_offsets[N_NODES + 1];
__device__ int    g_cursor[N_NODES];
__device__ int2   g_edges[E_EDGES];     // (src | t_act<<20, w bits), CSR by dst

// counts + decoupled-lookback scan state, zeroed in one cudaMemsetAsync
struct ScanState {
    int counts[N_NODES];
    int agg[NPART];
    int pre[NPART];
    int flag[NPART];     // 0=invalid, 1=aggregate ready, 2=prefix ready
};
__device__ ScanState g_ss;

// ---------------------------------------------------------------------------
__global__ void count_kernel(const int* __restrict__ edge_index) {
    int e = blockIdx.x * blockDim.x + threadIdx.x;
    if (e < E_EDGES) atomicAdd(&g_ss.counts[edge_index[E_EDGES + e]], 1);
}

// ---- single-kernel decoupled-lookback exclusive scan -> g_offsets/g_cursor
__global__ __launch_bounds__(256) void scan_kernel() {
    __shared__ int wsum[8];
    __shared__ int base_s;
    int b = blockIdx.x, tid = threadIdx.x;
    int lane = tid & 31, wid = tid >> 5;
    int i = b * 256 + tid;
    int v = (i < N_NODES) ? g_ss.counts[i] : 0;

    // block-wide inclusive scan of v
    int xi = v;
    #pragma unroll
    for (int o = 1; o < 32; o <<= 1) {
        int y = __shfl_up_sync(0xffffffffu, xi, o);
        if (lane >= o) xi += y;
    }
    if (lane == 31) wsum[wid] = xi;
    __syncthreads();
    if (tid == 0) {
        int a = 0;
        #pragma unroll
        for (int w = 0; w < 8; w++) { int t = wsum[w]; wsum[w] = a; a += t; }
    }
    __syncthreads();
    int excl = wsum[wid] + xi - v;        // exclusive within block

    if (tid == 255) {
        int total = excl + v;
        if (b == 0) {
            g_ss.pre[0] = total;
            __threadfence();
            atomicExch(&g_ss.flag[0], 2);
            base_s = 0;
        } else {
            g_ss.agg[b] = total;
            __threadfence();
            atomicExch(&g_ss.flag[b], 1);
            int base = 0;
            for (int j = b - 1; ; ) {
                int f;
                do { f = atomicAdd(&g_ss.flag[j], 0); } while (f == 0);
                if (f == 2) { base += atomicAdd(&g_ss.pre[j], 0); break; }
                base += atomicAdd(&g_ss.agg[j], 0);
                j--;
            }
            g_ss.pre[b] = base + total;
            __threadfence();
            atomicExch(&g_ss.flag[b], 2);
            base_s = base;
        }
        if (b == NPART - 1) g_offsets[N_NODES] = base_s + total;
    }
    __syncthreads();
    int off = base_s + excl;
    if (i < N_NODES) { g_offsets[i] = off; g_cursor[i] = off; }
}

// ---------------------------------------------------------------------------
__global__ void fill_kernel(const int* __restrict__ edge_index,
                            const float* __restrict__ edge_time,
                            const float* __restrict__ node_time,
                            const float* __restrict__ edge_weight) {
    int e = blockIdx.x * blockDim.x + threadIdx.x;
    if (e >= E_EDGES) return;
    int   src = edge_index[e];
    int   dst = edge_index[E_EDGES + e];
    float et  = edge_time[e];
    int tact = 0;
    #pragma unroll
    for (int t = 0; t < T_STEPS; t++) tact += (__ldg(&node_time[t]) < et) ? 1 : 0;
    int pos = atomicAdd(&g_cursor[dst], 1);
    g_edges[pos] = make_int2(src | (tact << 20), __float_as_int(edge_weight[e]));
}

// ---------------------------------------------------------------------------
// y = x @ W via wmma (HMMA): 256 threads = 8 warps, 128 rows/block.
__global__ __launch_bounds__(256) void gemm_wmma_kernel(const float* __restrict__ x,
                                                        const float* __restrict__ W,
                                                        int row_base) {
    using namespace nvcuda;
    __shared__ __half xh[128 * 80];
    __shared__ __half Wh[64 * 80];
    int tid  = threadIdx.x;
    int warp = tid >> 5;
    size_t row0 = (size_t)row_base + (size_t)blockIdx.x * 128;

    for (int i = tid; i < 64 * 16; i += 256) {
        int r = i >> 4, c = (i & 15) * 4;
        float4 v = ((const float4*)W)[i];
        __half2* p = (__half2*)(Wh + r * 80 + c);
        p[0] = __floats2half2_rn(v.x, v.y);
        p[1] = __floats2half2_rn(v.z, v.w);
    }
    for (int i = tid; i < 128 * 16; i += 256) {
        int r = i >> 4, c = (i & 15) * 4;
        float4 v = *(const float4*)(x + (row0 + r) * DD + c);
        __half2* p = (__half2*)(xh + r * 80 + c);
        p[0] = __floats2half2_rn(v.x, v.y);
        p[1] = __floats2half2_rn(v.z, v.w);
    }
    __syncthreads();

    wmma::fragment<wmma::accumulator, 16, 16, 16, float> acc[4];
    #pragma unroll
    for (int n = 0; n < 4; n++) wmma::fill_fragment(acc[n], 0.0f);

    #pragma unroll
    for (int k = 0; k < 4; k++) {
        wmma::fragment<wmma::matrix_a, 16, 16, 16, __half, wmma::row_major> af;
        wmma::load_matrix_sync(af, xh + (warp * 16) * 80 + k * 16, 80);
        #pragma unroll
        for (int n = 0; n < 4; n++) {
            wmma::fragment<wmma::matrix_b, 16, 16, 16, __half, wmma::row_major> bf;
            wmma::load_matrix_sync(bf, Wh + (k * 16) * 80 + n * 16, 80);
            wmma::mma_sync(acc[n], af, bf, acc[n]);
        }
    }

    #pragma unroll
    for (int n = 0; n < 4; n++) {
        wmma::fragment<wmma::accumulator, 16, 16, 16, __half> hacc;
        #pragma unroll
        for (int i = 0; i < hacc.num_elements; i++)
            hacc.x[i] = __float2half(acc[n].x[i]);
        wmma::store_matrix_sync(g_y + (row0 + warp * 16) * DD + n * 16,
                                hacc, DD, wmma::mem_row_major);
    }
}

// ---------------------------------------------------------------------------
// Gather: one warp per dst node, all 8 timesteps together, lane owns 2 cols.
__device__ __forceinline__ void gather_body(int2 m, int lane, float2 acc[T_STEPS]) {
    int   tact = m.x >> 20;                 // 8 => never active; predicates kill loads
    int   src  = m.x & 0xFFFFF;
    float w    = __int_as_float(m.y);
    const __half2* yp = (const __half2*)(g_y + (size_t)src * DD) + lane;
    #pragma unroll
    for (int t = 0; t < T_STEPS; t++) {
        if (t >= tact) {
            __half2 h = yp[t * (N_NODES * DD / 2)];
            float2  f = __half22float2(h);
            acc[t].x += w * f.x;
            acc[t].y += w * f.y;
        }
    }
}

__global__ __launch_bounds__(256) void gather_kernel(const float* __restrict__ bias,
                                                     float* __restrict__ out) {
    int gwarp = (blockIdx.x * blockDim.x + threadIdx.x) >> 5;
    int lane  = threadIdx.x & 31;
    if (gwarp >= N_NODES) return;
    int node = gwarp;

    int off0 = g_offsets[node];
    int off1 = g_offsets[node + 1];

    float2 acc[T_STEPS];
    #pragma unroll
    for (int t = 0; t < T_STEPS; t++) { acc[t].x = 0.f; acc[t].y = 0.f; }

    int e = off0;
    for (; e + 3 < off1; e += 4) {
        int2 m0 = g_edges[e];
        int2 m1 = g_edges[e + 1];
        int2 m2 = g_edges[e + 2];
        int2 m3 = g_edges[e + 3];
        gather_body(m0, lane, acc);
        gather_body(m1, lane, acc);
        gather_body(m2, lane, acc);
        gather_body(m3, lane, acc);
    }
    for (; e < off1; e++) gather_body(g_edges[e], lane, acc);

    float2 bb = *(const float2*)(bias + lane * 2);
    #pragma unroll
    for (int t = 0; t < T_STEPS; t++) {
        float2 o;
        o.x = acc[t].x + bb.x;
        o.y = acc[t].y + bb.y;
        *(float2*)(out + ((size_t)t * N_NODES + node) * DD + lane * 2) = o;
    }
}

// ---------------------------------------------------------------------------
extern "C" void kernel_launch(void* const* d_in, const int* in_sizes, int n_in,
                              void* d_out, int out_size) {
    const float* x           = (const float*)d_in[0];   // [T, N, 64]
    const int*   edge_index  = (const int*)  d_in[1];   // [2, E]
    const float* edge_time   = (const float*)d_in[2];   // [E]
    const float* node_time   = (const float*)d_in[3];   // [T]
    const float* edge_weight = (const float*)d_in[4];   // [E]
    const float* W           = (const float*)d_in[5];   // [64, 64]
    const float* bias        = (const float*)d_in[6];   // [64]
    float* out = (float*)d_out;                         // [T, N, 64]

    // zero counts + scan state in one memset (graph-capturable stream op)
    void* ss_ptr = nullptr;
    cudaGetSymbolAddress(&ss_ptr, g_ss);
    cudaMemsetAsync(ss_ptr, 0, sizeof(ScanState));

    // 1) CSR by dst (kernels 1-3)
    count_kernel<<<(E_EDGES + 255) / 256, 256>>>(edge_index);
    scan_kernel<<<NPART, 256>>>();
    fill_kernel<<<(E_EDGES + 255) / 256, 256>>>(edge_index, edge_time, node_time, edge_weight);

    // 2) y = x @ W  (tensor cores, fp16 out) — split so gather is launch #6 for ncu
    gemm_wmma_kernel<<<1562, 256>>>(x, W, 0);         // rows [0, 199936)
    gemm_wmma_kernel<<<1563, 256>>>(x, W, 199936);    // rows [199936, 400000)

    // 3) out[t, i] = b + sum_{e in CSR[i], t >= tact(e)} w_e * y[t, src_e]
    gather_kernel<<<(N_NODES * 32 + 255) / 256, 256>>>(bias, out);
}

// round 4
// speedup vs baseline: 1.0736x; 1.0736x over previous
#include <cuda_runtime.h>
#include <cuda_fp16.h>
#include <mma.h>

// Problem constants (fixed by the dataset)
#define T_STEPS 8
#define N_NODES 50000
#define E_EDGES 800000
#define DD 64
#define NPART ((N_NODES + 255) / 256)   // 196 scan blocks

// -------- scratch (static __device__ arrays; no allocation allowed) --------
__device__ __half g_y[(size_t)T_STEPS * N_NODES * DD];   // 51.2 MB, fp16 y = x@W
__device__ int    g_offsets[N_NODES + 1];
__device__ int    g_cursor[N_NODES];
__device__ int2   g_edges[E_EDGES];     // (src | t_act<<20, w bits), CSR by dst

// counts + decoupled-lookback scan state, zeroed in one cudaMemsetAsync
struct ScanState {
    int counts[N_NODES];
    int agg[NPART];
    int pre[NPART];
    int flag[NPART];     // 0=invalid, 1=aggregate ready, 2=prefix ready
};
__device__ ScanState g_ss;

// ---------------------------------------------------------------------------
// Kernel 1: y = x @ W via wmma (HMMA), 128 rows/block, 3125 blocks.
// FUSED: each of the 800000 threads also counts one edge's dst (CSR phase 1).
// Smem stride 72 halves (144 B): row-to-row phase offset 16 B -> conflict-free
// ldmatrix fragment loads.
__global__ __launch_bounds__(256) void gemm_count_kernel(const float* __restrict__ x,
                                                         const float* __restrict__ W,
                                                         const int* __restrict__ edge_index) {
    using namespace nvcuda;
    __shared__ __half xh[128 * 72];
    __shared__ __half Wh[64 * 72];
    int tid  = threadIdx.x;
    int warp = tid >> 5;
    size_t row0 = (size_t)blockIdx.x * 128;

    // fused edge count (exactly one edge per thread; grid*block == E_EDGES)
    int e = blockIdx.x * 256 + tid;
    atomicAdd(&g_ss.counts[edge_index[E_EDGES + e]], 1);

    // stage W (64x64) as half, stride 72
    for (int i = tid; i < 64 * 16; i += 256) {
        int r = i >> 4, c = (i & 15) * 4;
        float4 v = ((const float4*)W)[i];
        __half2* p = (__half2*)(Wh + r * 72 + c);
        p[0] = __floats2half2_rn(v.x, v.y);
        p[1] = __floats2half2_rn(v.z, v.w);
    }
    // stage x tile (128x64) as half, stride 72
    for (int i = tid; i < 128 * 16; i += 256) {
        int r = i >> 4, c = (i & 15) * 4;
        float4 v = *(const float4*)(x + (row0 + r) * DD + c);
        __half2* p = (__half2*)(xh + r * 72 + c);
        p[0] = __floats2half2_rn(v.x, v.y);
        p[1] = __floats2half2_rn(v.z, v.w);
    }
    __syncthreads();

    wmma::fragment<wmma::accumulator, 16, 16, 16, float> acc[4];
    #pragma unroll
    for (int n = 0; n < 4; n++) wmma::fill_fragment(acc[n], 0.0f);

    #pragma unroll
    for (int k = 0; k < 4; k++) {
        wmma::fragment<wmma::matrix_a, 16, 16, 16, __half, wmma::row_major> af;
        wmma::load_matrix_sync(af, xh + (warp * 16) * 72 + k * 16, 72);
        #pragma unroll
        for (int n = 0; n < 4; n++) {
            wmma::fragment<wmma::matrix_b, 16, 16, 16, __half, wmma::row_major> bf;
            wmma::load_matrix_sync(bf, Wh + (k * 16) * 72 + n * 16, 72);
            wmma::mma_sync(acc[n], af, bf, acc[n]);
        }
    }

    #pragma unroll
    for (int n = 0; n < 4; n++) {
        wmma::fragment<wmma::accumulator, 16, 16, 16, __half> hacc;
        #pragma unroll
        for (int i = 0; i < hacc.num_elements; i++)
            hacc.x[i] = __float2half(acc[n].x[i]);
        wmma::store_matrix_sync(g_y + (row0 + warp * 16) * DD + n * 16,
                                hacc, DD, wmma::mem_row_major);
    }
}

// ---------------------------------------------------------------------------
// Kernel 2: single-kernel decoupled-lookback exclusive scan -> offsets/cursor
__global__ __launch_bounds__(256) void scan_kernel() {
    __shared__ int wsum[8];
    __shared__ int base_s;
    int b = blockIdx.x, tid = threadIdx.x;
    int lane = tid & 31, wid = tid >> 5;
    int i = b * 256 + tid;
    int v = (i < N_NODES) ? g_ss.counts[i] : 0;

    int xi = v;
    #pragma unroll
    for (int o = 1; o < 32; o <<= 1) {
        int y = __shfl_up_sync(0xffffffffu, xi, o);
        if (lane >= o) xi += y;
    }
    if (lane == 31) wsum[wid] = xi;
    __syncthreads();
    if (tid == 0) {
        int a = 0;
        #pragma unroll
        for (int w = 0; w < 8; w++) { int t = wsum[w]; wsum[w] = a; a += t; }
    }
    __syncthreads();
    int excl = wsum[wid] + xi - v;

    if (tid == 255) {
        int total = excl + v;
        if (b == 0) {
            g_ss.pre[0] = total;
            __threadfence();
            atomicExch(&g_ss.flag[0], 2);
            base_s = 0;
        } else {
            g_ss.agg[b] = total;
            __threadfence();
            atomicExch(&g_ss.flag[b], 1);
            int base = 0;
            for (int j = b - 1; ; ) {
                int f;
                do { f = atomicAdd(&g_ss.flag[j], 0); } while (f == 0);
                if (f == 2) { base += atomicAdd(&g_ss.pre[j], 0); break; }
                base += atomicAdd(&g_ss.agg[j], 0);
                j--;
            }
            g_ss.pre[b] = base + total;
            __threadfence();
            atomicExch(&g_ss.flag[b], 2);
            base_s = base;
        }
        if (b == NPART - 1) g_offsets[N_NODES] = base_s + total;
    }
    __syncthreads();
    int off = base_s + excl;
    if (i < N_NODES) { g_offsets[i] = off; g_cursor[i] = off; }
}

// ---------------------------------------------------------------------------
// Kernel 3: place edges into CSR with activation index + weight packed
__global__ void fill_kernel(const int* __restrict__ edge_index,
                            const float* __restrict__ edge_time,
                            const float* __restrict__ node_time,
                            const float* __restrict__ edge_weight) {
    int e = blockIdx.x * blockDim.x + threadIdx.x;
    if (e >= E_EDGES) return;
    int   src = edge_index[e];
    int   dst = edge_index[E_EDGES + e];
    float et  = edge_time[e];
    int tact = 0;
    #pragma unroll
    for (int t = 0; t < T_STEPS; t++) tact += (__ldg(&node_time[t]) < et) ? 1 : 0;
    int pos = atomicAdd(&g_cursor[dst], 1);
    g_edges[pos] = make_int2(src | (tact << 20), __float_as_int(edge_weight[e]));
}

// ---------------------------------------------------------------------------
// Kernel 4: gather — one warp per dst node, all 8 timesteps together,
// lane owns 2 cols, x4 edge unroll for MLP.
__device__ __forceinline__ void gather_body(int2 m, int lane, float2 acc[T_STEPS]) {
    int   tact = m.x >> 20;                 // 8 => never active; predicates kill loads
    int   src  = m.x & 0xFFFFF;
    float w    = __int_as_float(m.y);
    const __half2* yp = (const __half2*)(g_y + (size_t)src * DD) + lane;
    #pragma unroll
    for (int t = 0; t < T_STEPS; t++) {
        if (t >= tact) {
            __half2 h = yp[t * (N_NODES * DD / 2)];
            float2  f = __half22float2(h);
            acc[t].x += w * f.x;
            acc[t].y += w * f.y;
        }
    }
}

__global__ __launch_bounds__(256) void gather_kernel(const float* __restrict__ bias,
                                                     float* __restrict__ out) {
    int gwarp = (blockIdx.x * blockDim.x + threadIdx.x) >> 5;
    int lane  = threadIdx.x & 31;
    if (gwarp >= N_NODES) return;
    int node = gwarp;

    int off0 = g_offsets[node];
    int off1 = g_offsets[node + 1];

    float2 acc[T_STEPS];
    #pragma unroll
    for (int t = 0; t < T_STEPS; t++) { acc[t].x = 0.f; acc[t].y = 0.f; }

    int e = off0;
    for (; e + 3 < off1; e += 4) {
        int2 m0 = g_edges[e];
        int2 m1 = g_edges[e + 1];
        int2 m2 = g_edges[e + 2];
        int2 m3 = g_edges[e + 3];
        gather_body(m0, lane, acc);
        gather_body(m1, lane, acc);
        gather_body(m2, lane, acc);
        gather_body(m3, lane, acc);
    }
    for (; e < off1; e++) gather_body(g_edges[e], lane, acc);

    float2 bb = *(const float2*)(bias + lane * 2);
    #pragma unroll
    for (int t = 0; t < T_STEPS; t++) {
        float2 o;
        o.x = acc[t].x + bb.x;
        o.y = acc[t].y + bb.y;
        *(float2*)(out + ((size_t)t * N_NODES + node) * DD + lane * 2) = o;
    }
}

// ---------------------------------------------------------------------------
extern "C" void kernel_launch(void* const* d_in, const int* in_sizes, int n_in,
                              void* d_out, int out_size) {
    const float* x           = (const float*)d_in[0];   // [T, N, 64]
    const int*   edge_index  = (const int*)  d_in[1];   // [2, E]
    const float* edge_time   = (const float*)d_in[2];   // [E]
    const float* node_time   = (const float*)d_in[3];   // [T]
    const float* edge_weight = (const float*)d_in[4];   // [E]
    const float* W           = (const float*)d_in[5];   // [64, 64]
    const float* bias        = (const float*)d_in[6];   // [64]
    float* out = (float*)d_out;                         // [T, N, 64]

    // zero counts + scan state in one memset (graph-capturable stream op)
    void* ss_ptr = nullptr;
    cudaGetSymbolAddress(&ss_ptr, g_ss);
    cudaMemsetAsync(ss_ptr, 0, sizeof(ScanState));

    // 1) y = x @ W (tensor cores) + fused edge counting (800000 threads == E)
    gemm_count_kernel<<<3125, 256>>>(x, W, edge_index);

    // 2) CSR offsets
    scan_kernel<<<NPART, 256>>>();

    // 3) CSR fill
    fill_kernel<<<(E_EDGES + 255) / 256, 256>>>(edge_index, edge_time, node_time, edge_weight);

    // 4) out[t, i] = b + sum_{e in CSR[i], t >= tact(e)} w_e * y[t, src_e]
    gather_kernel<<<(N_NODES * 32 + 255) / 256, 256>>>(bias, out);
}

// round 5
// speedup vs baseline: 1.1540x; 1.0750x over previous
#include <cuda_runtime.h>
#include <cuda_fp16.h>
#include <mma.h>

// Problem constants (fixed by the dataset)
#define T_STEPS 8
#define N_NODES 50000
#define E_EDGES 800000
#define DD 64
#define NPART ((N_NODES + 255) / 256)   // 196 scan blocks

// -------- scratch (static __device__ arrays; no allocation allowed) --------
// y laid out [node][t][64]  -> node stride = 512 halves = 1024 B,
// so all 8 timestep rows of a src are contiguous (immediate LDG offsets).
__device__ __half g_y[(size_t)N_NODES * T_STEPS * DD];   // 51.2 MB
__device__ int    g_offsets[N_NODES + 1];
__device__ int    g_cursor[N_NODES];
__device__ int2   g_edges[E_EDGES];     // (src | t_act<<20, w bits), CSR by dst

// counts + decoupled-lookback scan state, zeroed in one cudaMemsetAsync
struct ScanState {
    int counts[N_NODES];
    int agg[NPART];
    int pre[NPART];
    int flag[NPART];     // 0=invalid, 1=aggregate ready, 2=prefix ready
};
__device__ ScanState g_ss;

// ---------------------------------------------------------------------------
// Kernel 1: y = x @ W via wmma (HMMA), 128 rows/block, 3125 blocks.
// FUSED: each of the 800000 threads also counts one edge's dst (CSR phase 1).
// Output stored transposed to [node][t][64]. Each 16-row warp fragment has a
// single t (50000 % 16 == 0), consecutive nodes -> ldm = 512.
__global__ __launch_bounds__(256) void gemm_count_kernel(const float* __restrict__ x,
                                                         const float* __restrict__ W,
                                                         const int* __restrict__ edge_index) {
    using namespace nvcuda;
    __shared__ __half xh[128 * 72];
    __shared__ __half Wh[64 * 72];
    int tid  = threadIdx.x;
    int warp = tid >> 5;
    size_t row0 = (size_t)blockIdx.x * 128;

    // fused edge count (exactly one edge per thread; grid*block == E_EDGES)
    int e = blockIdx.x * 256 + tid;
    atomicAdd(&g_ss.counts[edge_index[E_EDGES + e]], 1);

    // stage W (64x64) as half, stride 72 (conflict-free ldmatrix phases)
    for (int i = tid; i < 64 * 16; i += 256) {
        int r = i >> 4, c = (i & 15) * 4;
        float4 v = ((const float4*)W)[i];
        __half2* p = (__half2*)(Wh + r * 72 + c);
        p[0] = __floats2half2_rn(v.x, v.y);
        p[1] = __floats2half2_rn(v.z, v.w);
    }
    // stage x tile (128x64) as half, stride 72
    for (int i = tid; i < 128 * 16; i += 256) {
        int r = i >> 4, c = (i & 15) * 4;
        float4 v = *(const float4*)(x + (row0 + r) * DD + c);
        __half2* p = (__half2*)(xh + r * 72 + c);
        p[0] = __floats2half2_rn(v.x, v.y);
        p[1] = __floats2half2_rn(v.z, v.w);
    }
    __syncthreads();

    wmma::fragment<wmma::accumulator, 16, 16, 16, float> acc[4];
    #pragma unroll
    for (int n = 0; n < 4; n++) wmma::fill_fragment(acc[n], 0.0f);

    #pragma unroll
    for (int k = 0; k < 4; k++) {
        wmma::fragment<wmma::matrix_a, 16, 16, 16, __half, wmma::row_major> af;
        wmma::load_matrix_sync(af, xh + (warp * 16) * 72 + k * 16, 72);
        #pragma unroll
        for (int n = 0; n < 4; n++) {
            wmma::fragment<wmma::matrix_b, 16, 16, 16, __half, wmma::row_major> bf;
            wmma::load_matrix_sync(bf, Wh + (k * 16) * 72 + n * 16, 72);
            wmma::mma_sync(acc[n], af, bf, acc[n]);
        }
    }

    // transposed store: input row r = t*N + node  ->  g_y[node*8*64 + t*64]
    int r = (int)row0 + warp * 16;
    int t = r / N_NODES;
    int node0 = r - t * N_NODES;
    __half* dst = g_y + (size_t)node0 * (T_STEPS * DD) + t * DD;
    #pragma unroll
    for (int n = 0; n < 4; n++) {
        wmma::fragment<wmma::accumulator, 16, 16, 16, __half> hacc;
        #pragma unroll
        for (int i = 0; i < hacc.num_elements; i++)
            hacc.x[i] = __float2half(acc[n].x[i]);
        wmma::store_matrix_sync(dst + n * 16, hacc, T_STEPS * DD, wmma::mem_row_major);
    }
}

// ---------------------------------------------------------------------------
// Kernel 2: single-kernel decoupled-lookback exclusive scan -> offsets/cursor
__global__ __launch_bounds__(256) void scan_kernel() {
    __shared__ int wsum[8];
    __shared__ int base_s;
    int b = blockIdx.x, tid = threadIdx.x;
    int lane = tid & 31, wid = tid >> 5;
    int i = b * 256 + tid;
    int v = (i < N_NODES) ? g_ss.counts[i] : 0;

    int xi = v;
    #pragma unroll
    for (int o = 1; o < 32; o <<= 1) {
        int y = __shfl_up_sync(0xffffffffu, xi, o);
        if (lane >= o) xi += y;
    }
    if (lane == 31) wsum[wid] = xi;
    __syncthreads();
    if (tid == 0) {
        int a = 0;
        #pragma unroll
        for (int w = 0; w < 8; w++) { int t = wsum[w]; wsum[w] = a; a += t; }
    }
    __syncthreads();
    int excl = wsum[wid] + xi - v;

    if (tid == 255) {
        int total = excl + v;
        if (b == 0) {
            g_ss.pre[0] = total;
            __threadfence();
            atomicExch(&g_ss.flag[0], 2);
            base_s = 0;
        } else {
            g_ss.agg[b] = total;
            __threadfence();
            atomicExch(&g_ss.flag[b], 1);
            int base = 0;
            for (int j = b - 1; ; ) {
                int f;
                do { f = atomicAdd(&g_ss.flag[j], 0); } while (f == 0);
                if (f == 2) { base += atomicAdd(&g_ss.pre[j], 0); break; }
                base += atomicAdd(&g_ss.agg[j], 0);
                j--;
            }
            g_ss.pre[b] = base + total;
            __threadfence();
            atomicExch(&g_ss.flag[b], 2);
            base_s = base;
        }
        if (b == NPART - 1) g_offsets[N_NODES] = base_s + total;
    }
    __syncthreads();
    int off = base_s + excl;
    if (i < N_NODES) { g_offsets[i] = off; g_cursor[i] = off; }
}

// ---------------------------------------------------------------------------
// Kernel 3: place edges into CSR with activation index + weight packed
__global__ void fill_kernel(const int* __restrict__ edge_index,
                            const float* __restrict__ edge_time,
                            const float* __restrict__ node_time,
                            const float* __restrict__ edge_weight) {
    int e = blockIdx.x * blockDim.x + threadIdx.x;
    if (e >= E_EDGES) return;
    int   src = edge_index[e];
    int   dst = edge_index[E_EDGES + e];
    float et  = edge_time[e];
    int tact = 0;
    #pragma unroll
    for (int t = 0; t < T_STEPS; t++) tact += (__ldg(&node_time[t]) < et) ? 1 : 0;
    int pos = atomicAdd(&g_cursor[dst], 1);
    g_edges[pos] = make_int2(src | (tact << 20), __float_as_int(edge_weight[e]));
}

// ---------------------------------------------------------------------------
// Kernel 4: gather — one warp per dst node.
// Lane mapping: slot = lane>>3 (t-slot 0..3), cg = lane&7 (cols 8*cg..8*cg+7).
// Two iterations tp=0,1 cover t = tp*4+slot. Each active lane does one
// LDG.128 (8 halves); a slot-group of 8 lanes covers one 128B t-row; the
// warp covers 4 contiguous t-rows per load (512B) -> fully coalesced.
__device__ __forceinline__ void gather_edge(int2 m, const char* ybase, int slot,
                                            float acc[2][8]) {
    int   tact = m.x >> 20;                 // 8 => never active
    int   src  = m.x & 0xFFFFF;
    float w    = __int_as_float(m.y);
    const char* p = ybase + ((size_t)src << 10);   // node stride 1024 B
    #pragma unroll
    for (int tp = 0; tp < 2; tp++) {
        if (tp * 4 + slot >= tact) {
            uint4 h = *(const uint4*)(p + tp * 512);
            float2 f0 = __half22float2(*(const __half2*)&h.x);
            float2 f1 = __half22float2(*(const __half2*)&h.y);
            float2 f2 = __half22float2(*(const __half2*)&h.z);
            float2 f3 = __half22float2(*(const __half2*)&h.w);
            acc[tp][0] += w * f0.x; acc[tp][1] += w * f0.y;
            acc[tp][2] += w * f1.x; acc[tp][3] += w * f1.y;
            acc[tp][4] += w * f2.x; acc[tp][5] += w * f2.y;
            acc[tp][6] += w * f3.x; acc[tp][7] += w * f3.y;
        }
    }
}

__global__ __launch_bounds__(256) void gather_kernel(const float* __restrict__ bias,
                                                     float* __restrict__ out) {
    int gwarp = (blockIdx.x * blockDim.x + threadIdx.x) >> 5;
    int lane  = threadIdx.x & 31;
    if (gwarp >= N_NODES) return;
    int node = gwarp;
    int slot = lane >> 3;        // t-slot 0..3
    int cg   = lane & 7;         // column group (8 cols)

    int off0 = g_offsets[node];
    int off1 = g_offsets[node + 1];

    float acc[2][8] = {};
    const char* ybase = (const char*)g_y + slot * 128 + cg * 16;

    int e = off0;
    for (; e + 1 < off1; e += 2) {
        int2 m0 = g_edges[e];
        int2 m1 = g_edges[e + 1];
        gather_edge(m0, ybase, slot, acc);
        gather_edge(m1, ybase, slot, acc);
    }
    if (e < off1) gather_edge(g_edges[e], ybase, slot, acc);

    float4 b0 = *(const float4*)(bias + cg * 8);
    float4 b1 = *(const float4*)(bias + cg * 8 + 4);
    #pragma unroll
    for (int tp = 0; tp < 2; tp++) {
        int t = tp * 4 + slot;
        float* op = out + ((size_t)t * N_NODES + node) * DD + cg * 8;
        float4 o0, o1;
        o0.x = acc[tp][0] + b0.x; o0.y = acc[tp][1] + b0.y;
        o0.z = acc[tp][2] + b0.z; o0.w = acc[tp][3] + b0.w;
        o1.x = acc[tp][4] + b1.x; o1.y = acc[tp][5] + b1.y;
        o1.z = acc[tp][6] + b1.z; o1.w = acc[tp][7] + b1.w;
        *(float4*)op       = o0;
        *(float4*)(op + 4) = o1;
    }
}

// ---------------------------------------------------------------------------
extern "C" void kernel_launch(void* const* d_in, const int* in_sizes, int n_in,
                              void* d_out, int out_size) {
    const float* x           = (const float*)d_in[0];   // [T, N, 64]
    const int*   edge_index  = (const int*)  d_in[1];   // [2, E]
    const float* edge_time   = (const float*)d_in[2];   // [E]
    const float* node_time   = (const float*)d_in[3];   // [T]
    const float* edge_weight = (const float*)d_in[4];   // [E]
    const float* W           = (const float*)d_in[5];   // [64, 64]
    const float* bias        = (const float*)d_in[6];   // [64]
    float* out = (float*)d_out;                         // [T, N, 64]

    // zero counts + scan state in one memset (graph-capturable stream op)
    void* ss_ptr = nullptr;
    cudaGetSymbolAddress(&ss_ptr, g_ss);
    cudaMemsetAsync(ss_ptr, 0, sizeof(ScanState));

    // 1) y = x @ W (tensor cores, transposed [N][T][64] fp16 out) + fused count
    gemm_count_kernel<<<3125, 256>>>(x, W, edge_index);

    // 2) CSR offsets
    scan_kernel<<<NPART, 256>>>();

    // 3) CSR fill
    fill_kernel<<<(E_EDGES + 255) / 256, 256>>>(edge_index, edge_time, node_time, edge_weight);

    // 4) out[t, i] = b + sum_{e in CSR[i], t >= tact(e)} w_e * y[src_e, t]
    gather_kernel<<<(N_NODES * 32 + 255) / 256, 256>>>(bias, out);
}